// round 16
// baseline (speedup 1.0000x reference)
#include <cuda_runtime.h>
#include <cuda_fp16.h>
#include <math.h>

#define NN 50000
#define EE 800000
#define DIN 20
#define DD 128
#define BN_EPS 1e-5f

#define SB 64
#define CHUNK 800
#define PT 4

#define APADH 136  // A smem row stride in halves (>=128; word-stride 68 => banks gid*4+tig)
#define BPADH 136  // B smem (n-major) row stride in halves, same conflict-free map
#define TC_ROWS 64
#define GTILES 4
#define TC_SMEM (size_t)((TC_ROWS * APADH + 128 * BPADH) * sizeof(__half))

typedef unsigned long long u64;
typedef unsigned int u32;

// ---------------- scratch ------------------------------------------------------
__device__ float g_h[NN * DD];        // pre-BN activations (fp32, stats path)
__device__ __half g_hh[NN * DD];      // post-BN h in fp16 (GEMM A operand)
__device__ __half g_kh[NN * DD];
__device__ __half g_qvh[NN * 2 * DD]; // per node: [lane4-group][q0..3, v0..3]
__device__ float g_agg[NN * DD];
__device__ float g_sum[3 * DD], g_sumsq[3 * DD];
__device__ int g_src[EE], g_dst[EE];
__device__ int g_deg[NN + 1];
__device__ int g_off[NN + 1];
__device__ int g_pos[NN];
__device__ int g_esrc[EE];
__device__ int g_bsum[SB], g_bpre[SB];
__device__ unsigned int g_or;

// ---------------- helpers ---------------------------------------------------------
__device__ __forceinline__ float fast_sigmoid(float x) {
    float t;
    asm("tanh.approx.f32 %0, %1;" : "=f"(t) : "f"(0.5f * x));
    return fmaf(0.5f, t, 0.5f);
}

// ---------------- init ------------------------------------------------------------
__global__ void init_kernel() {
    int i = blockIdx.x * blockDim.x + threadIdx.x;
    if (i == 0) g_or = 0u;
    if (i < 3 * DD) {
        g_sum[i] = 0.f;
        g_sumsq[i] = 0.f;
    }
    if (i <= NN) g_deg[i] = 0;
}

__global__ void detect_kernel(const unsigned int* __restrict__ w) {
    unsigned int v = 0;
    for (long long i = blockIdx.x * (long long)blockDim.x + threadIdx.x;
         i < EE; i += (long long)gridDim.x * blockDim.x)
        v |= w[2 * i + 1];
#pragma unroll
    for (int o = 16; o > 0; o >>= 1) v |= __shfl_xor_sync(0xffffffffu, v, o);
    if ((threadIdx.x & 31) == 0 && v) atomicOr(&g_or, v);
}

__global__ void convert_kernel(const int* __restrict__ ei) {
    int i = blockIdx.x * blockDim.x + threadIdx.x;
    if (i >= EE) return;
    int s, d;
    if (g_or == 0u) {
        const long long* e64 = (const long long*)ei;
        s = (int)e64[i];
        d = (int)e64[EE + i];
    } else {
        s = ei[i];
        d = ei[EE + i];
    }
    g_src[i] = s;
    g_dst[i] = d;
    atomicAdd(&g_deg[d], 1);
}

// ---------------- exclusive scan (3 kernels) ---------------------------------------
__global__ void scan1_kernel() {
    __shared__ int sh[256];
    int b = blockIdx.x, t = threadIdx.x;
    int base = b * CHUNK + t * PT;
    int s = 0;
#pragma unroll
    for (int j = 0; j < PT; j++) {
        int idx = base + j;
        if (idx < b * CHUNK + CHUNK && idx < NN) s += g_deg[idx];
    }
    sh[t] = s;
    __syncthreads();
    for (int o = 128; o > 0; o >>= 1) {
        if (t < o) sh[t] += sh[t + o];
        __syncthreads();
    }
    if (t == 0) g_bsum[b] = sh[0];
}

__global__ void scan2_kernel() {
    __shared__ int sh[SB];
    int t = threadIdx.x;
    sh[t] = g_bsum[t];
    __syncthreads();
    if (t == 0) {
        int run = 0;
        for (int i = 0; i < SB; i++) {
            int v = sh[i];
            sh[i] = run;
            run += v;
        }
    }
    __syncthreads();
    g_bpre[t] = sh[t];
}

__global__ void scan3_kernel() {
    __shared__ int arr[256];
    int b = blockIdx.x, t = threadIdx.x;
    int base = b * CHUNK + t * PT;
    int dv[PT];
    int tsum = 0;
#pragma unroll
    for (int j = 0; j < PT; j++) {
        int idx = base + j;
        dv[j] = (idx < b * CHUNK + CHUNK && idx < NN) ? g_deg[idx] : 0;
        tsum += dv[j];
    }
    arr[t] = tsum;
    __syncthreads();
#pragma unroll
    for (int o = 1; o < 256; o <<= 1) {
        int v = (t >= o) ? arr[t - o] : 0;
        __syncthreads();
        arr[t] += v;
        __syncthreads();
    }
    int run = g_bpre[b] + arr[t] - tsum;
#pragma unroll
    for (int j = 0; j < PT; j++) {
        int idx = base + j;
        if (idx < b * CHUNK + CHUNK && idx < NN) {
            g_off[idx] = run;
            g_pos[idx] = run;
            run += dv[j];
        }
    }
    if (b == 0 && t == 0) g_off[NN] = EE;
}

__global__ void scatter_kernel() {
    int i = blockIdx.x * blockDim.x + threadIdx.x;
    if (i >= EE) return;
    int d = g_dst[i];
    int p = atomicAdd(&g_pos[d], 1);
    g_esrc[p] = g_src[i];
}

// ---------------- pre-MP linear + fused stage-0 BN stats --------------------------
#define PL_ROWS 32
__global__ void pre_linear_kernel(const float* __restrict__ x,
                                  const float* __restrict__ w) {
    __shared__ float xs[PL_ROWS][DIN];
    __shared__ float ssum[DD], ssq[DD];
    int t = threadIdx.x;
    int c = t & 127;
    int rl = t >> 7;
    float wr[DIN];
#pragma unroll
    for (int kk = 0; kk < DIN; kk++) wr[kk] = w[kk * DD + c];
    if (t < DD) {
        ssum[t] = 0.f;
        ssq[t] = 0.f;
    }
    int row0 = blockIdx.x * PL_ROWS;
    for (int i = t; i < PL_ROWS * DIN; i += 256) {
        int rr = i / DIN, kk = i % DIN;
        int grow = row0 + rr;
        xs[rr][kk] = (grow < NN) ? x[(size_t)grow * DIN + kk] : 0.f;
    }
    __syncthreads();
    float s = 0.f, s2 = 0.f;
#pragma unroll 4
    for (int r2 = 0; r2 < PL_ROWS; r2 += 2) {
        int r = r2 + rl;
        int grow = row0 + r;
        float a0 = 0.f, a1 = 0.f, a2 = 0.f, a3 = 0.f;
#pragma unroll
        for (int kk = 0; kk < 20; kk += 4) {
            a0 = fmaf(xs[r][kk + 0], wr[kk + 0], a0);
            a1 = fmaf(xs[r][kk + 1], wr[kk + 1], a1);
            a2 = fmaf(xs[r][kk + 2], wr[kk + 2], a2);
            a3 = fmaf(xs[r][kk + 3], wr[kk + 3], a3);
        }
        float acc = (a0 + a1) + (a2 + a3);
        if (grow < NN) {
            g_h[(size_t)grow * DD + c] = acc;
            s += acc;
            s2 += acc * acc;
        }
    }
    atomicAdd(&ssum[c], s);
    atomicAdd(&ssq[c], s2);
    __syncthreads();
    if (t < DD) {
        atomicAdd(&g_sum[t], ssum[t]);
        atomicAdd(&g_sumsq[t], ssq[t]);
    }
}

// ---------------- fused BN finalize -> BN -> ReLU -> l2norm ------------------------
__global__ void bn_apply_kernel(int which, int stage,
                                const float* __restrict__ gamma,
                                const float* __restrict__ beta,
                                float* __restrict__ out_ext) {
    __shared__ float smu[DD], srs[DD];
    int t = threadIdx.x;
    if (t < DD) {
        float mu = g_sum[stage * DD + t] * (1.f / NN);
        float var = g_sumsq[stage * DD + t] * (1.f / NN) - mu * mu;
        smu[t] = mu;
        srs[t] = rsqrtf(var + BN_EPS) * gamma[t];
    }
    __syncthreads();
    const float* xp = which ? g_agg : g_h;
    int gt = blockIdx.x * blockDim.x + t;
    int row = gt >> 5;
    int lane = gt & 31;
    if (row >= NN) return;
    int c0 = lane * 4;
    float4 xv = *(const float4*)(xp + (size_t)row * DD + c0);
    float xsv[4] = {xv.x, xv.y, xv.z, xv.w};
    float y[4];
    float ss = 0.f;
#pragma unroll
    for (int j = 0; j < 4; j++) {
        int c = c0 + j;
        float val = (xsv[j] - smu[c]) * srs[c] + beta[c];
        val = fmaxf(val, 0.f);
        y[j] = val;
        ss += val * val;
    }
#pragma unroll
    for (int o = 16; o > 0; o >>= 1) ss += __shfl_xor_sync(0xffffffffu, ss, o);
    float sc = 1.f / fmaxf(sqrtf(ss), 1e-12f);
    if (out_ext) {
        float4 ov = make_float4(y[0] * sc, y[1] * sc, y[2] * sc, y[3] * sc);
        *(float4*)(out_ext + (size_t)row * DD + c0) = ov;
    } else {
        __half2 h01 = __floats2half2_rn(y[0] * sc, y[1] * sc);
        __half2 h23 = __floats2half2_rn(y[2] * sc, y[3] * sc);
        *(__half2*)(g_hh + (size_t)row * DD + c0) = h01;
        *(__half2*)(g_hh + (size_t)row * DD + c0 + 2) = h23;
    }
}

// ---------------- tensor-core GEMM: fp16 m16n8k16, weight-stationary --------------
// grid (4, ceil(NN/(64*GTILES))); blockIdx.x = matrix {k,q,v,skip}.
// A (post-BN h) fp16 in gmem; B transposed to n-major fp16 at one-time fill.
// smem 52.2KB -> 4 blocks/SM; LDS bytes and MMA count halved vs tf32.
__global__ void __launch_bounds__(256)
gemm_tc_kernel(const float* __restrict__ wkp, const float* __restrict__ wqp,
               const float* __restrict__ wvp, const float* __restrict__ wsp) {
    extern __shared__ __half smh[];
    __half* Bs = smh;                     // [128 n][BPADH k-halves]
    __half* As = smh + 128 * BPADH;       // [64 row][APADH k-halves]
    int t = threadIdx.x;
    int mat = blockIdx.x;
    const float* W = (mat == 0) ? wkp : (mat == 1) ? wqp : (mat == 2) ? wvp : wsp;

    // One-time B fill with transpose: Bs[n][k] = (half)W[k][n].
#pragma unroll
    for (int i = 0; i < 16; i++) {
        int idx = t + 256 * i;
        int k = idx >> 5, n4 = (idx & 31) * 4;
        float4 v = *(const float4*)(W + k * DD + n4);
        Bs[(n4 + 0) * BPADH + k] = __float2half_rn(v.x);
        Bs[(n4 + 1) * BPADH + k] = __float2half_rn(v.y);
        Bs[(n4 + 2) * BPADH + k] = __float2half_rn(v.z);
        Bs[(n4 + 3) * BPADH + k] = __float2half_rn(v.w);
    }
    __syncthreads();

    int lane = t & 31, wid = t >> 5;
    int gid = lane >> 2, tig = lane & 3;
    int wm = wid >> 2, wn = wid & 3;

    const __half* Ab = As + (wm * 32 + gid) * APADH + 2 * tig;

    for (int g = 0; g < GTILES; g++) {
        int row0 = (blockIdx.y * GTILES + g) * TC_ROWS;
        if (row0 >= NN) break;

        // A fill: 64 rows x 128 halves, uint4 (8 halves) per slot.
#pragma unroll
        for (int i = 0; i < 4; i++) {
            int idx = t + 256 * i;
            int r = idx >> 4, c8 = (idx & 15) * 8;
            int grow = row0 + r;
            uint4 v = make_uint4(0u, 0u, 0u, 0u);
            if (grow < NN) v = *(const uint4*)(g_hh + (size_t)grow * DD + c8);
            *(uint4*)(As + r * APADH + c8) = v;
        }
        __syncthreads();

        float c[2][4][4];
#pragma unroll
        for (int mi = 0; mi < 2; mi++)
#pragma unroll
            for (int nj = 0; nj < 4; nj++)
#pragma unroll
                for (int r = 0; r < 4; r++) c[mi][nj][r] = 0.f;

#pragma unroll
        for (int ks = 0; ks < 8; ks++) {
            int k0 = ks * 16;
            u32 a[2][4];
#pragma unroll
            for (int mi = 0; mi < 2; mi++) {
                const __half* p = Ab + mi * 16 * APADH + k0;
                a[mi][0] = *(const u32*)(p);
                a[mi][1] = *(const u32*)(p + 8 * APADH);
                a[mi][2] = *(const u32*)(p + 8);
                a[mi][3] = *(const u32*)(p + 8 * APADH + 8);
            }
            u32 b[4][2];
#pragma unroll
            for (int nj = 0; nj < 4; nj++) {
                const __half* p =
                    Bs + (wn * 32 + nj * 8 + gid) * BPADH + 2 * tig + k0;
                b[nj][0] = *(const u32*)(p);
                b[nj][1] = *(const u32*)(p + 8);
            }
#pragma unroll
            for (int mi = 0; mi < 2; mi++)
#pragma unroll
                for (int nj = 0; nj < 4; nj++) {
                    asm volatile(
                        "mma.sync.aligned.m16n8k16.row.col.f32.f16.f16.f32 "
                        "{%0,%1,%2,%3}, {%4,%5,%6,%7}, {%8,%9}, {%0,%1,%2,%3};"
                        : "+f"(c[mi][nj][0]), "+f"(c[mi][nj][1]),
                          "+f"(c[mi][nj][2]), "+f"(c[mi][nj][3])
                        : "r"(a[mi][0]), "r"(a[mi][1]), "r"(a[mi][2]),
                          "r"(a[mi][3]), "r"(b[nj][0]), "r"(b[nj][1]));
                }
        }

        int orow = row0 + wm * 32 + gid;
#pragma unroll
        for (int mi = 0; mi < 2; mi++) {
            int r0 = orow + mi * 16;
#pragma unroll
            for (int nj = 0; nj < 4; nj++) {
                int col = wn * 32 + nj * 8 + 2 * tig;
                __half2 h01 = __floats2half2_rn(c[mi][nj][0], c[mi][nj][1]);
                __half2 h23 = __floats2half2_rn(c[mi][nj][2], c[mi][nj][3]);
                if (mat == 0) {
                    if (r0 < NN) *(__half2*)(g_kh + (size_t)r0 * DD + col) = h01;
                    if (r0 + 8 < NN)
                        *(__half2*)(g_kh + (size_t)(r0 + 8) * DD + col) = h23;
                } else if (mat == 1 || mat == 2) {
                    size_t base =
                        (size_t)(col >> 2) * 8 + (col & 3) + (mat == 2 ? 4 : 0);
                    if (r0 < NN) *(__half2*)(g_qvh + (size_t)r0 * 256 + base) = h01;
                    if (r0 + 8 < NN)
                        *(__half2*)(g_qvh + (size_t)(r0 + 8) * 256 + base) = h23;
                } else {
                    if (r0 < NN)
                        *(float2*)(g_agg + (size_t)r0 * DD + col) =
                            make_float2(c[mi][nj][0], c[mi][nj][1]);
                    if (r0 + 8 < NN)
                        *(float2*)(g_agg + (size_t)(r0 + 8) * DD + col) =
                            make_float2(c[mi][nj][2], c[mi][nj][3]);
                }
            }
        }
        __syncthreads();
    }
}

// ---------------- CSR aggregation: warp per dst + fused BN stats -------------------
__device__ __forceinline__ void edge_accum(int s, float2 kf0, float2 kf1,
                                           float& a0, float& a1, float& a2,
                                           float& a3, int lane) {
    uint4 qv = __ldg((const uint4*)(g_qvh + (size_t)s * 256 + lane * 8));
    float2 qa = __half22float2(*(__half2*)&qv.x);
    float2 qb = __half22float2(*(__half2*)&qv.y);
    float2 va = __half22float2(*(__half2*)&qv.z);
    float2 vb = __half22float2(*(__half2*)&qv.w);
    a0 = fmaf(va.x, fast_sigmoid(kf0.x + qa.x), a0);
    a1 = fmaf(va.y, fast_sigmoid(kf0.y + qa.y), a1);
    a2 = fmaf(vb.x, fast_sigmoid(kf1.x + qb.x), a2);
    a3 = fmaf(vb.y, fast_sigmoid(kf1.y + qb.y), a3);
}

__global__ void agg_kernel(int stage) {
    __shared__ float ssum[DD], ssq[DD];
    int t = threadIdx.x;
    if (t < DD) {
        ssum[t] = 0.f;
        ssq[t] = 0.f;
    }
    __syncthreads();
    int lane = t & 31;
    int c0 = lane * 4;
    int gw = (blockIdx.x * blockDim.x + t) >> 5;
    int nwarps = (gridDim.x * blockDim.x) >> 5;
    float st[4] = {0.f, 0.f, 0.f, 0.f};
    float sq[4] = {0.f, 0.f, 0.f, 0.f};

    for (int n = gw; n < NN; n += nwarps) {
        int beg = __ldg(g_off + n);
        int end = __ldg(g_off + n + 1);
        uint2 kraw = __ldg((const uint2*)(g_kh + (size_t)n * DD + c0));
        float2 kf0 = __half22float2(*(__half2*)&kraw.x);
        float2 kf1 = __half22float2(*(__half2*)&kraw.y);
        float a0 = 0.f, a1 = 0.f, a2 = 0.f, a3 = 0.f;
        int e = beg;
        for (; e + 4 <= end; e += 4) {
            int s0 = __ldg(g_esrc + e);
            int s1 = __ldg(g_esrc + e + 1);
            int s2 = __ldg(g_esrc + e + 2);
            int s3 = __ldg(g_esrc + e + 3);
            edge_accum(s0, kf0, kf1, a0, a1, a2, a3, lane);
            edge_accum(s1, kf0, kf1, a0, a1, a2, a3, lane);
            edge_accum(s2, kf0, kf1, a0, a1, a2, a3, lane);
            edge_accum(s3, kf0, kf1, a0, a1, a2, a3, lane);
        }
        for (; e < end; e++) {
            int s0 = __ldg(g_esrc + e);
            edge_accum(s0, kf0, kf1, a0, a1, a2, a3, lane);
        }
        float* ap = g_agg + (size_t)n * DD + c0;
        float4 skip = *(const float4*)ap;
        float o0 = skip.x + a0, o1 = skip.y + a1, o2 = skip.z + a2, o3 = skip.w + a3;
        *(float4*)ap = make_float4(o0, o1, o2, o3);
        st[0] += o0; st[1] += o1; st[2] += o2; st[3] += o3;
        sq[0] += o0 * o0; sq[1] += o1 * o1; sq[2] += o2 * o2; sq[3] += o3 * o3;
    }
#pragma unroll
    for (int j = 0; j < 4; j++) {
        atomicAdd(&ssum[c0 + j], st[j]);
        atomicAdd(&ssq[c0 + j], sq[j]);
    }
    __syncthreads();
    if (t < DD) {
        atomicAdd(&g_sum[stage * DD + t], ssum[t]);
        atomicAdd(&g_sumsq[stage * DD + t], ssq[t]);
    }
}

// ---------------- launch -------------------------------------------------------------
extern "C" void kernel_launch(void* const* d_in, const int* in_sizes, int n_in,
                              void* d_out, int out_size) {
    const float* x     = (const float*)d_in[0];
    const int*   ei    = (const int*)d_in[1];
    const float* pre_w = (const float*)d_in[2];
    const float* pre_g = (const float*)d_in[3];
    const float* pre_b = (const float*)d_in[4];
    const float* wk    = (const float*)d_in[5];
    const float* wq    = (const float*)d_in[6];
    const float* wv    = (const float*)d_in[7];
    const float* ws    = (const float*)d_in[8];
    const float* mg    = (const float*)d_in[9];
    const float* mb    = (const float*)d_in[10];
    float* outp = (float*)d_out;

    cudaFuncSetAttribute(gemm_tc_kernel,
                         cudaFuncAttributeMaxDynamicSharedMemorySize,
                         (int)TC_SMEM);

    const int n_tiles = (NN + TC_ROWS - 1) / TC_ROWS;          // 782
    const int gemm_gy = (n_tiles + GTILES - 1) / GTILES;        // 196

    init_kernel<<<(NN + 256) / 256, 256>>>();
    pre_linear_kernel<<<(NN + PL_ROWS - 1) / PL_ROWS, 256>>>(x, pre_w);
    bn_apply_kernel<<<(NN + 7) / 8, 256>>>(0, 0, pre_g, pre_b, nullptr);
    gemm_tc_kernel<<<dim3(4, gemm_gy), 256, TC_SMEM>>>(wk, wq, wv, ws);

    detect_kernel<<<256, 256>>>((const unsigned int*)ei);
    convert_kernel<<<(EE + 255) / 256, 256>>>(ei);
    scan1_kernel<<<SB, 256>>>();
    scan2_kernel<<<1, SB>>>();
    scan3_kernel<<<SB, 256>>>();
    scatter_kernel<<<(EE + 255) / 256, 256>>>();

    for (int l = 0; l < 2; l++) {
        if (l > 0)
            gemm_tc_kernel<<<dim3(4, gemm_gy), 256, TC_SMEM>>>(
                wk + l * DD * DD, wq + l * DD * DD, wv + l * DD * DD,
                ws + l * DD * DD);
        agg_kernel<<<1184, 256>>>(1 + l);
        bn_apply_kernel<<<(NN + 7) / 8, 256>>>(
            1, 1 + l, mg + l * DD, mb + l * DD, (l == 1) ? outp : nullptr);
    }
}

// round 17
// speedup vs baseline: 1.0084x; 1.0084x over previous
#include <cuda_runtime.h>
#include <cuda_fp16.h>
#include <math.h>

#define NN 50000
#define EE 800000
#define DIN 20
#define DD 128
#define BN_EPS 1e-5f

#define SB 64
#define CHUNK 800
#define PT 4

#define APADH 136  // A smem row stride in halves (word-stride 68 -> conflict-free frags)
#define BPADH 136  // B smem (n-major) row stride in halves
#define TC_ROWS 64
#define GTILES 4
#define TC_SMEM (size_t)((TC_ROWS * APADH + 128 * BPADH) * sizeof(__half))

typedef unsigned long long u64;
typedef unsigned int u32;

// ---------------- scratch ------------------------------------------------------
__device__ float g_h[NN * DD];        // pre-BN activations (fp32, stats path)
__device__ __half g_hh[NN * DD];      // post-BN h in fp16 (GEMM A operand)
__device__ __half g_kh[NN * DD];
__device__ __half g_qvh[NN * 2 * DD]; // per node: [lane4-group][q0..3, v0..3]
__device__ float g_agg[NN * DD];
__device__ float g_sum[3 * DD], g_sumsq[3 * DD];
__device__ int g_src[EE], g_dst[EE];
__device__ int g_deg[NN + 1];
__device__ int g_off[NN + 1];
__device__ int g_pos[NN];
__device__ int g_esrc[EE];
__device__ int g_bsum[SB], g_bpre[SB];
__device__ unsigned int g_or;

// ---------------- helpers ---------------------------------------------------------
__device__ __forceinline__ float fast_sigmoid(float x) {
    float t;
    asm("tanh.approx.f32 %0, %1;" : "=f"(t) : "f"(0.5f * x));
    return fmaf(0.5f, t, 0.5f);
}

// ---------------- init ------------------------------------------------------------
__global__ void init_kernel() {
    int i = blockIdx.x * blockDim.x + threadIdx.x;
    if (i == 0) g_or = 0u;
    if (i < 3 * DD) {
        g_sum[i] = 0.f;
        g_sumsq[i] = 0.f;
    }
    if (i <= NN) g_deg[i] = 0;
}

__global__ void detect_kernel(const unsigned int* __restrict__ w) {
    unsigned int v = 0;
    for (long long i = blockIdx.x * (long long)blockDim.x + threadIdx.x;
         i < EE; i += (long long)gridDim.x * blockDim.x)
        v |= w[2 * i + 1];
#pragma unroll
    for (int o = 16; o > 0; o >>= 1) v |= __shfl_xor_sync(0xffffffffu, v, o);
    if ((threadIdx.x & 31) == 0 && v) atomicOr(&g_or, v);
}

__global__ void convert_kernel(const int* __restrict__ ei) {
    int i = blockIdx.x * blockDim.x + threadIdx.x;
    if (i >= EE) return;
    int s, d;
    if (g_or == 0u) {
        const long long* e64 = (const long long*)ei;
        s = (int)e64[i];
        d = (int)e64[EE + i];
    } else {
        s = ei[i];
        d = ei[EE + i];
    }
    g_src[i] = s;
    g_dst[i] = d;
    atomicAdd(&g_deg[d], 1);
}

// ---------------- exclusive scan (3 kernels) ---------------------------------------
__global__ void scan1_kernel() {
    __shared__ int sh[256];
    int b = blockIdx.x, t = threadIdx.x;
    int base = b * CHUNK + t * PT;
    int s = 0;
#pragma unroll
    for (int j = 0; j < PT; j++) {
        int idx = base + j;
        if (idx < b * CHUNK + CHUNK && idx < NN) s += g_deg[idx];
    }
    sh[t] = s;
    __syncthreads();
    for (int o = 128; o > 0; o >>= 1) {
        if (t < o) sh[t] += sh[t + o];
        __syncthreads();
    }
    if (t == 0) g_bsum[b] = sh[0];
}

__global__ void scan2_kernel() {
    __shared__ int sh[SB];
    int t = threadIdx.x;
    sh[t] = g_bsum[t];
    __syncthreads();
    if (t == 0) {
        int run = 0;
        for (int i = 0; i < SB; i++) {
            int v = sh[i];
            sh[i] = run;
            run += v;
        }
    }
    __syncthreads();
    g_bpre[t] = sh[t];
}

__global__ void scan3_kernel() {
    __shared__ int arr[256];
    int b = blockIdx.x, t = threadIdx.x;
    int base = b * CHUNK + t * PT;
    int dv[PT];
    int tsum = 0;
#pragma unroll
    for (int j = 0; j < PT; j++) {
        int idx = base + j;
        dv[j] = (idx < b * CHUNK + CHUNK && idx < NN) ? g_deg[idx] : 0;
        tsum += dv[j];
    }
    arr[t] = tsum;
    __syncthreads();
#pragma unroll
    for (int o = 1; o < 256; o <<= 1) {
        int v = (t >= o) ? arr[t - o] : 0;
        __syncthreads();
        arr[t] += v;
        __syncthreads();
    }
    int run = g_bpre[b] + arr[t] - tsum;
#pragma unroll
    for (int j = 0; j < PT; j++) {
        int idx = base + j;
        if (idx < b * CHUNK + CHUNK && idx < NN) {
            g_off[idx] = run;
            g_pos[idx] = run;
            run += dv[j];
        }
    }
    if (b == 0 && t == 0) g_off[NN] = EE;
}

__global__ void scatter_kernel() {
    int i = blockIdx.x * blockDim.x + threadIdx.x;
    if (i >= EE) return;
    int d = g_dst[i];
    int p = atomicAdd(&g_pos[d], 1);
    g_esrc[p] = g_src[i];
}

// ---------------- pre-MP linear + fused stage-0 BN stats --------------------------
#define PL_ROWS 32
__global__ void pre_linear_kernel(const float* __restrict__ x,
                                  const float* __restrict__ w) {
    __shared__ float xs[PL_ROWS][DIN];
    __shared__ float ssum[DD], ssq[DD];
    int t = threadIdx.x;
    int c = t & 127;
    int rl = t >> 7;
    float wr[DIN];
#pragma unroll
    for (int kk = 0; kk < DIN; kk++) wr[kk] = w[kk * DD + c];
    if (t < DD) {
        ssum[t] = 0.f;
        ssq[t] = 0.f;
    }
    int row0 = blockIdx.x * PL_ROWS;
    for (int i = t; i < PL_ROWS * DIN; i += 256) {
        int rr = i / DIN, kk = i % DIN;
        int grow = row0 + rr;
        xs[rr][kk] = (grow < NN) ? x[(size_t)grow * DIN + kk] : 0.f;
    }
    __syncthreads();
    float s = 0.f, s2 = 0.f;
#pragma unroll 4
    for (int r2 = 0; r2 < PL_ROWS; r2 += 2) {
        int r = r2 + rl;
        int grow = row0 + r;
        float a0 = 0.f, a1 = 0.f, a2 = 0.f, a3 = 0.f;
#pragma unroll
        for (int kk = 0; kk < 20; kk += 4) {
            a0 = fmaf(xs[r][kk + 0], wr[kk + 0], a0);
            a1 = fmaf(xs[r][kk + 1], wr[kk + 1], a1);
            a2 = fmaf(xs[r][kk + 2], wr[kk + 2], a2);
            a3 = fmaf(xs[r][kk + 3], wr[kk + 3], a3);
        }
        float acc = (a0 + a1) + (a2 + a3);
        if (grow < NN) {
            g_h[(size_t)grow * DD + c] = acc;
            s += acc;
            s2 += acc * acc;
        }
    }
    atomicAdd(&ssum[c], s);
    atomicAdd(&ssq[c], s2);
    __syncthreads();
    if (t < DD) {
        atomicAdd(&g_sum[t], ssum[t]);
        atomicAdd(&g_sumsq[t], ssq[t]);
    }
}

// ---------------- fused BN finalize -> BN -> ReLU -> l2norm ------------------------
__global__ void bn_apply_kernel(int which, int stage,
                                const float* __restrict__ gamma,
                                const float* __restrict__ beta,
                                float* __restrict__ out_ext) {
    __shared__ float smu[DD], srs[DD];
    int t = threadIdx.x;
    if (t < DD) {
        float mu = g_sum[stage * DD + t] * (1.f / NN);
        float var = g_sumsq[stage * DD + t] * (1.f / NN) - mu * mu;
        smu[t] = mu;
        srs[t] = rsqrtf(var + BN_EPS) * gamma[t];
    }
    __syncthreads();
    const float* xp = which ? g_agg : g_h;
    int gt = blockIdx.x * blockDim.x + t;
    int row = gt >> 5;
    int lane = gt & 31;
    if (row >= NN) return;
    int c0 = lane * 4;
    float4 xv = *(const float4*)(xp + (size_t)row * DD + c0);
    float xsv[4] = {xv.x, xv.y, xv.z, xv.w};
    float y[4];
    float ss = 0.f;
#pragma unroll
    for (int j = 0; j < 4; j++) {
        int c = c0 + j;
        float val = (xsv[j] - smu[c]) * srs[c] + beta[c];
        val = fmaxf(val, 0.f);
        y[j] = val;
        ss += val * val;
    }
#pragma unroll
    for (int o = 16; o > 0; o >>= 1) ss += __shfl_xor_sync(0xffffffffu, ss, o);
    float sc = 1.f / fmaxf(sqrtf(ss), 1e-12f);
    if (out_ext) {
        float4 ov = make_float4(y[0] * sc, y[1] * sc, y[2] * sc, y[3] * sc);
        *(float4*)(out_ext + (size_t)row * DD + c0) = ov;
    } else {
        __half2 h01 = __floats2half2_rn(y[0] * sc, y[1] * sc);
        __half2 h23 = __floats2half2_rn(y[2] * sc, y[3] * sc);
        *(__half2*)(g_hh + (size_t)row * DD + c0) = h01;
        *(__half2*)(g_hh + (size_t)row * DD + c0 + 2) = h23;
    }
}

// ---------------- tensor-core GEMM: fp16 m16n8k16 + ldmatrix fragments ------------
// grid (4, ceil(NN/(64*GTILES))); blockIdx.x = matrix {k,q,v,skip}.
// Fragment loads via LDSM: per k-step 2x ldmatrix.x4 (A) + 4x ldmatrix.x2 (B)
// instead of 16 scalar LDS.32 -> LSU issue pressure cut ~2.7x.
__global__ void __launch_bounds__(256)
gemm_tc_kernel(const float* __restrict__ wkp, const float* __restrict__ wqp,
               const float* __restrict__ wvp, const float* __restrict__ wsp) {
    extern __shared__ __half smh[];
    __half* Bs = smh;                     // [128 n][BPADH k-halves]
    __half* As = smh + 128 * BPADH;       // [64 row][APADH k-halves]
    int t = threadIdx.x;
    int mat = blockIdx.x;
    const float* W = (mat == 0) ? wkp : (mat == 1) ? wqp : (mat == 2) ? wvp : wsp;

    // One-time B fill with transpose: Bs[n][k] = (half)W[k][n].
#pragma unroll
    for (int i = 0; i < 16; i++) {
        int idx = t + 256 * i;
        int k = idx >> 5, n4 = (idx & 31) * 4;
        float4 v = *(const float4*)(W + k * DD + n4);
        Bs[(n4 + 0) * BPADH + k] = __float2half_rn(v.x);
        Bs[(n4 + 1) * BPADH + k] = __float2half_rn(v.y);
        Bs[(n4 + 2) * BPADH + k] = __float2half_rn(v.z);
        Bs[(n4 + 3) * BPADH + k] = __float2half_rn(v.w);
    }
    __syncthreads();

    int lane = t & 31, wid = t >> 5;
    int gid = lane >> 2, tig = lane & 3;
    int wm = wid >> 2, wn = wid & 3;

    // LDSM base addresses (byte offsets in shared state space).
    u32 smA = (u32)__cvta_generic_to_shared(As);
    u32 smB = (u32)__cvta_generic_to_shared(Bs);
    // A: row = wm*32 + mi*16 + (lane&15); col-halves = k0 + (lane>>4)*8
    u32 aAddr0 = smA + (((wm * 32 + (lane & 15)) * APADH + (lane >> 4) * 8) << 1);
    // B: row n = wn*32 + nj*8 + (lane&7); col-halves = k0 + ((lane>>3)&1)*8
    u32 bAddr0 = smB + (((wn * 32 + (lane & 7)) * BPADH + ((lane >> 3) & 1) * 8) << 1);

    for (int g = 0; g < GTILES; g++) {
        int row0 = (blockIdx.y * GTILES + g) * TC_ROWS;
        if (row0 >= NN) break;

        // A fill: 64 rows x 128 halves, uint4 (8 halves) per slot.
#pragma unroll
        for (int i = 0; i < 4; i++) {
            int idx = t + 256 * i;
            int r = idx >> 4, c8 = (idx & 15) * 8;
            int grow = row0 + r;
            uint4 v = make_uint4(0u, 0u, 0u, 0u);
            if (grow < NN) v = *(const uint4*)(g_hh + (size_t)grow * DD + c8);
            *(uint4*)(As + r * APADH + c8) = v;
        }
        __syncthreads();

        float c[2][4][4];
#pragma unroll
        for (int mi = 0; mi < 2; mi++)
#pragma unroll
            for (int nj = 0; nj < 4; nj++)
#pragma unroll
                for (int r = 0; r < 4; r++) c[mi][nj][r] = 0.f;

#pragma unroll
        for (int ks = 0; ks < 8; ks++) {
            int k0 = ks * 16;
            u32 a[2][4];
#pragma unroll
            for (int mi = 0; mi < 2; mi++) {
                u32 addr = aAddr0 + ((mi * 16 * APADH + k0) << 1);
                asm volatile(
                    "ldmatrix.sync.aligned.m8n8.x4.shared.b16 "
                    "{%0,%1,%2,%3}, [%4];"
                    : "=r"(a[mi][0]), "=r"(a[mi][1]), "=r"(a[mi][2]),
                      "=r"(a[mi][3])
                    : "r"(addr));
            }
            u32 b[4][2];
#pragma unroll
            for (int nj = 0; nj < 4; nj++) {
                u32 addr = bAddr0 + ((nj * 8 * BPADH + k0) << 1);
                asm volatile(
                    "ldmatrix.sync.aligned.m8n8.x2.shared.b16 {%0,%1}, [%2];"
                    : "=r"(b[nj][0]), "=r"(b[nj][1])
                    : "r"(addr));
            }
#pragma unroll
            for (int mi = 0; mi < 2; mi++)
#pragma unroll
                for (int nj = 0; nj < 4; nj++) {
                    asm volatile(
                        "mma.sync.aligned.m16n8k16.row.col.f32.f16.f16.f32 "
                        "{%0,%1,%2,%3}, {%4,%5,%6,%7}, {%8,%9}, {%0,%1,%2,%3};"
                        : "+f"(c[mi][nj][0]), "+f"(c[mi][nj][1]),
                          "+f"(c[mi][nj][2]), "+f"(c[mi][nj][3])
                        : "r"(a[mi][0]), "r"(a[mi][1]), "r"(a[mi][2]),
                          "r"(a[mi][3]), "r"(b[nj][0]), "r"(b[nj][1]));
                }
        }

        int orow = row0 + wm * 32 + gid;
#pragma unroll
        for (int mi = 0; mi < 2; mi++) {
            int r0 = orow + mi * 16;
#pragma unroll
            for (int nj = 0; nj < 4; nj++) {
                int col = wn * 32 + nj * 8 + 2 * tig;
                __half2 h01 = __floats2half2_rn(c[mi][nj][0], c[mi][nj][1]);
                __half2 h23 = __floats2half2_rn(c[mi][nj][2], c[mi][nj][3]);
                if (mat == 0) {
                    if (r0 < NN) *(__half2*)(g_kh + (size_t)r0 * DD + col) = h01;
                    if (r0 + 8 < NN)
                        *(__half2*)(g_kh + (size_t)(r0 + 8) * DD + col) = h23;
                } else if (mat == 1 || mat == 2) {
                    size_t base =
                        (size_t)(col >> 2) * 8 + (col & 3) + (mat == 2 ? 4 : 0);
                    if (r0 < NN) *(__half2*)(g_qvh + (size_t)r0 * 256 + base) = h01;
                    if (r0 + 8 < NN)
                        *(__half2*)(g_qvh + (size_t)(r0 + 8) * 256 + base) = h23;
                } else {
                    if (r0 < NN)
                        *(float2*)(g_agg + (size_t)r0 * DD + col) =
                            make_float2(c[mi][nj][0], c[mi][nj][1]);
                    if (r0 + 8 < NN)
                        *(float2*)(g_agg + (size_t)(r0 + 8) * DD + col) =
                            make_float2(c[mi][nj][2], c[mi][nj][3]);
                }
            }
        }
        __syncthreads();
    }
}

// ---------------- CSR aggregation: warp per dst + fused BN stats -------------------
__device__ __forceinline__ void edge_accum(int s, float2 kf0, float2 kf1,
                                           float& a0, float& a1, float& a2,
                                           float& a3, int lane) {
    uint4 qv = __ldg((const uint4*)(g_qvh + (size_t)s * 256 + lane * 8));
    float2 qa = __half22float2(*(__half2*)&qv.x);
    float2 qb = __half22float2(*(__half2*)&qv.y);
    float2 va = __half22float2(*(__half2*)&qv.z);
    float2 vb = __half22float2(*(__half2*)&qv.w);
    a0 = fmaf(va.x, fast_sigmoid(kf0.x + qa.x), a0);
    a1 = fmaf(va.y, fast_sigmoid(kf0.y + qa.y), a1);
    a2 = fmaf(vb.x, fast_sigmoid(kf1.x + qb.x), a2);
    a3 = fmaf(vb.y, fast_sigmoid(kf1.y + qb.y), a3);
}

__global__ void agg_kernel(int stage) {
    __shared__ float ssum[DD], ssq[DD];
    int t = threadIdx.x;
    if (t < DD) {
        ssum[t] = 0.f;
        ssq[t] = 0.f;
    }
    __syncthreads();
    int lane = t & 31;
    int c0 = lane * 4;
    int gw = (blockIdx.x * blockDim.x + t) >> 5;
    int nwarps = (gridDim.x * blockDim.x) >> 5;
    float st[4] = {0.f, 0.f, 0.f, 0.f};
    float sq[4] = {0.f, 0.f, 0.f, 0.f};

    for (int n = gw; n < NN; n += nwarps) {
        int beg = __ldg(g_off + n);
        int end = __ldg(g_off + n + 1);
        uint2 kraw = __ldg((const uint2*)(g_kh + (size_t)n * DD + c0));
        float2 kf0 = __half22float2(*(__half2*)&kraw.x);
        float2 kf1 = __half22float2(*(__half2*)&kraw.y);
        float a0 = 0.f, a1 = 0.f, a2 = 0.f, a3 = 0.f;
        int e = beg;
        for (; e + 4 <= end; e += 4) {
            int s0 = __ldg(g_esrc + e);
            int s1 = __ldg(g_esrc + e + 1);
            int s2 = __ldg(g_esrc + e + 2);
            int s3 = __ldg(g_esrc + e + 3);
            edge_accum(s0, kf0, kf1, a0, a1, a2, a3, lane);
            edge_accum(s1, kf0, kf1, a0, a1, a2, a3, lane);
            edge_accum(s2, kf0, kf1, a0, a1, a2, a3, lane);
            edge_accum(s3, kf0, kf1, a0, a1, a2, a3, lane);
        }
        for (; e < end; e++) {
            int s0 = __ldg(g_esrc + e);
            edge_accum(s0, kf0, kf1, a0, a1, a2, a3, lane);
        }
        float* ap = g_agg + (size_t)n * DD + c0;
        float4 skip = *(const float4*)ap;
        float o0 = skip.x + a0, o1 = skip.y + a1, o2 = skip.z + a2, o3 = skip.w + a3;
        *(float4*)ap = make_float4(o0, o1, o2, o3);
        st[0] += o0; st[1] += o1; st[2] += o2; st[3] += o3;
        sq[0] += o0 * o0; sq[1] += o1 * o1; sq[2] += o2 * o2; sq[3] += o3 * o3;
    }
#pragma unroll
    for (int j = 0; j < 4; j++) {
        atomicAdd(&ssum[c0 + j], st[j]);
        atomicAdd(&ssq[c0 + j], sq[j]);
    }
    __syncthreads();
    if (t < DD) {
        atomicAdd(&g_sum[stage * DD + t], ssum[t]);
        atomicAdd(&g_sumsq[stage * DD + t], ssq[t]);
    }
}

// ---------------- launch -------------------------------------------------------------
extern "C" void kernel_launch(void* const* d_in, const int* in_sizes, int n_in,
                              void* d_out, int out_size) {
    const float* x     = (const float*)d_in[0];
    const int*   ei    = (const int*)d_in[1];
    const float* pre_w = (const float*)d_in[2];
    const float* pre_g = (const float*)d_in[3];
    const float* pre_b = (const float*)d_in[4];
    const float* wk    = (const float*)d_in[5];
    const float* wq    = (const float*)d_in[6];
    const float* wv    = (const float*)d_in[7];
    const float* ws    = (const float*)d_in[8];
    const float* mg    = (const float*)d_in[9];
    const float* mb    = (const float*)d_in[10];
    float* outp = (float*)d_out;

    cudaFuncSetAttribute(gemm_tc_kernel,
                         cudaFuncAttributeMaxDynamicSharedMemorySize,
                         (int)TC_SMEM);

    const int n_tiles = (NN + TC_ROWS - 1) / TC_ROWS;          // 782
    const int gemm_gy = (n_tiles + GTILES - 1) / GTILES;        // 196

    init_kernel<<<(NN + 256) / 256, 256>>>();
    pre_linear_kernel<<<(NN + PL_ROWS - 1) / PL_ROWS, 256>>>(x, pre_w);
    bn_apply_kernel<<<(NN + 7) / 8, 256>>>(0, 0, pre_g, pre_b, nullptr);
    gemm_tc_kernel<<<dim3(4, gemm_gy), 256, TC_SMEM>>>(wk, wq, wv, ws);

    detect_kernel<<<256, 256>>>((const unsigned int*)ei);
    convert_kernel<<<(EE + 255) / 256, 256>>>(ei);
    scan1_kernel<<<SB, 256>>>();
    scan2_kernel<<<1, SB>>>();
    scan3_kernel<<<SB, 256>>>();
    scatter_kernel<<<(EE + 255) / 256, 256>>>();

    for (int l = 0; l < 2; l++) {
        if (l > 0)
            gemm_tc_kernel<<<dim3(4, gemm_gy), 256, TC_SMEM>>>(
                wk + l * DD * DD, wq + l * DD * DD, wv + l * DD * DD,
                ws + l * DD * DD);
        agg_kernel<<<1184, 256>>>(1 + l);
        bn_apply_kernel<<<(NN + 7) / 8, 256>>>(
            1, 1 + l, mg + l * DD, mb + l * DD, (l == 1) ? outp : nullptr);
    }
}